// round 6
// baseline (speedup 1.0000x reference)
#include <cuda_runtime.h>
#include <cuda_fp16.h>
#include <cstdint>

// Problem dims: x (4,2048,4096) fp32 -> M=8192, qweight (4096,2048) int32,
// scale/zero (4096,32) fp32, out (8192,4096) fp32.
#define MDIM 8192
#define NDIM 4096
#define KDIM 4096
#define GROUPS 32

// Scratch (allocation-free rule: __device__ globals)
__device__ __align__(256) __half g_xh[(size_t)MDIM * KDIM];  // 64 MB
__device__ __align__(256) __half g_wh[(size_t)NDIM * KDIM];  // 32 MB

// ---------------------------------------------------------------------------
// Prep kernel 1: x fp32 -> fp16
// ---------------------------------------------------------------------------
__global__ void xconv_kernel(const float* __restrict__ x) {
    int i = blockIdx.x * blockDim.x + threadIdx.x;
    float4 v = reinterpret_cast<const float4*>(x)[i];
    union { uint2 u; __half2 h[2]; } pk;
    pk.h[0] = __floats2half2_rn(v.x, v.y);
    pk.h[1] = __floats2half2_rn(v.z, v.w);
    reinterpret_cast<uint2*>(g_xh)[i] = pk.u;
}

// ---------------------------------------------------------------------------
// Prep kernel 2: int4 group-dequant -> fp16 weights
// ---------------------------------------------------------------------------
__global__ void dequant_kernel(const int* __restrict__ qw,
                               const float* __restrict__ scale,
                               const float* __restrict__ zero) {
    int i = blockIdx.x * blockDim.x + threadIdx.x;
    int4 q = reinterpret_cast<const int4*>(qw)[i];
    int o  = i >> 9;
    int j4 = i & 511;
    int g  = (j4 * 8) >> 7;
    float s = scale[o * GROUPS + g];
    float z = zero [o * GROUPS + g];
    int v[4] = {q.x, q.y, q.z, q.w};
    union { uint4 u; __half2 h[4]; } pk;
#pragma unroll
    for (int t = 0; t < 4; ++t) {
        float lo = (float)( v[t]       & 0xF);
        float hi = (float)((v[t] >> 4) & 0xF);
        pk.h[t] = __floats2half2_rn((lo - z) * s, (hi - z) * s);
    }
    reinterpret_cast<uint4*>(g_wh)[i] = pk.u;
}

// ---------------------------------------------------------------------------
// fp16 GEMM (mma.sync HMMA path — tcgen05 rejected by compute_103 PTX target)
// CTA tile 128x256, BK=64, 3-stage cp.async pipeline, 8 warps (2x4),
// warp tile 64x64 -> 8 LDSM.x4 per 32 HMMA.
// ---------------------------------------------------------------------------
#define BM 128
#define BN 256
#define BK 64
#define NK (KDIM / BK)   // 64
#define STAGES 3
#define A_HALF (BM * BK)              // halves per A stage
#define B_HALF (BN * BK)
#define STAGE_HALF (A_HALF + B_HALF)  // 24576 halves = 48 KB
#define SMEM_TOTAL (STAGES * STAGE_HALF * 2)  // 147456 B

__device__ __forceinline__ void cp16(uint32_t s, const void* g) {
    asm volatile("cp.async.cg.shared.global [%0], [%1], 16;" :: "r"(s), "l"(g));
}
__device__ __forceinline__ void ldsm4(uint32_t& r0, uint32_t& r1, uint32_t& r2,
                                      uint32_t& r3, const __half* p) {
    uint32_t s = (uint32_t)__cvta_generic_to_shared(p);
    asm volatile("ldmatrix.sync.aligned.m8n8.x4.shared.b16 {%0,%1,%2,%3}, [%4];"
                 : "=r"(r0), "=r"(r1), "=r"(r2), "=r"(r3) : "r"(s));
}
__device__ __forceinline__ void mma16816(float* d, const uint32_t* a, const uint32_t* b) {
    asm volatile(
        "mma.sync.aligned.m16n8k16.row.col.f32.f16.f16.f32 "
        "{%0,%1,%2,%3}, {%4,%5,%6,%7}, {%8,%9}, {%0,%1,%2,%3};"
        : "+f"(d[0]), "+f"(d[1]), "+f"(d[2]), "+f"(d[3])
        : "r"(a[0]), "r"(a[1]), "r"(a[2]), "r"(a[3]), "r"(b[0]), "r"(b[1]));
}

__global__ void __launch_bounds__(256, 1) gemm_kernel(float* __restrict__ out) {
    extern __shared__ __half smem[];

    const int tid  = threadIdx.x;
    const int warp = tid >> 5;
    const int lane = tid & 31;
    const int wm = warp >> 2;   // 0..1  (64-row band)
    const int wn = warp & 3;    // 0..3  (64-col band)
    const int m0 = blockIdx.y * BM;
    const int n0 = blockIdx.x * BN;

    const __half* gA = g_xh + (size_t)m0 * KDIM;
    const __half* gB = g_wh + (size_t)n0 * KDIM;

    const int ldRow = tid >> 3;  // 0..31
    const int ldCh  = tid & 7;   // 16B chunk within 128B row

    float acc[4][8][4];
#pragma unroll
    for (int mt = 0; mt < 4; ++mt)
#pragma unroll
        for (int nt = 0; nt < 8; ++nt)
#pragma unroll
            for (int r = 0; r < 4; ++r) acc[mt][nt][r] = 0.0f;

    // --- stage loader (SW128 swizzle: chunk ^= row&7); 12 cp16/thread ---
    auto stage = [&](int buf, int k0) {
        __half* sA = smem + buf * STAGE_HALF;
        __half* sB = sA + A_HALF;
        uint32_t sAb = (uint32_t)__cvta_generic_to_shared(sA);
        uint32_t sBb = (uint32_t)__cvta_generic_to_shared(sB);
        const int sw = (ldCh ^ (ldRow & 7)) * 8;  // ldRow&7 invariant under +32
#pragma unroll
        for (int p = 0; p < 4; ++p) {
            int r = ldRow + p * 32;
            cp16(sAb + (uint32_t)(r * BK + sw) * 2, gA + (size_t)r * KDIM + k0 + ldCh * 8);
        }
#pragma unroll
        for (int p = 0; p < 8; ++p) {
            int r = ldRow + p * 32;
            cp16(sBb + (uint32_t)(r * BK + sw) * 2, gB + (size_t)r * KDIM + k0 + ldCh * 8);
        }
    };

    // prologue: fill STAGES-1 stages
#pragma unroll
    for (int s = 0; s < STAGES - 1; ++s) {
        stage(s, s * BK);
        asm volatile("cp.async.commit_group;");
    }

    for (int kt = 0; kt < NK; ++kt) {
        const int buf = kt % STAGES;
        if (kt + STAGES - 1 < NK) {
            stage((kt + STAGES - 1) % STAGES, (kt + STAGES - 1) * BK);
            asm volatile("cp.async.commit_group;");
            asm volatile("cp.async.wait_group %0;" :: "n"(STAGES - 1));
        } else {
            asm volatile("cp.async.wait_group 0;");
        }
        __syncthreads();

        const __half* bufA = smem + buf * STAGE_HALF;
        const __half* bufB = bufA + A_HALF;

#pragma unroll
        for (int ks = 0; ks < BK / 16; ++ks) {
            uint32_t aF[4][4];
#pragma unroll
            for (int mt = 0; mt < 4; ++mt) {
                int r  = wm * 64 + mt * 16 + (lane & 15);
                int ch = ks * 2 + (lane >> 4);
                const __half* p = bufA + r * BK + ((ch ^ (lane & 7)) * 8);
                ldsm4(aF[mt][0], aF[mt][1], aF[mt][2], aF[mt][3], p);
            }
            uint32_t bF[8][2];
#pragma unroll
            for (int nt2 = 0; nt2 < 4; ++nt2) {
                int r  = wn * 64 + nt2 * 16 + (lane & 7) + ((lane >> 4) << 3);
                int ch = ks * 2 + ((lane >> 3) & 1);
                const __half* p = bufB + r * BK + ((ch ^ (lane & 7)) * 8);
                uint32_t r0, r1, r2, r3;
                ldsm4(r0, r1, r2, r3, p);
                bF[nt2 * 2 + 0][0] = r0; bF[nt2 * 2 + 0][1] = r1;
                bF[nt2 * 2 + 1][0] = r2; bF[nt2 * 2 + 1][1] = r3;
            }
#pragma unroll
            for (int mt = 0; mt < 4; ++mt)
#pragma unroll
                for (int nt = 0; nt < 8; ++nt)
                    mma16816(acc[mt][nt], aF[mt], bF[nt]);
        }
        __syncthreads();
    }

    // --- epilogue: fp32 direct stores ---
    const int g  = lane >> 2;
    const int tg = lane & 3;
#pragma unroll
    for (int mt = 0; mt < 4; ++mt) {
        int row0 = m0 + wm * 64 + mt * 16;
#pragma unroll
        for (int nt = 0; nt < 8; ++nt) {
            int col = n0 + wn * 64 + nt * 8 + tg * 2;
            *reinterpret_cast<float2*>(out + (size_t)(row0 + g) * NDIM + col) =
                make_float2(acc[mt][nt][0], acc[mt][nt][1]);
            *reinterpret_cast<float2*>(out + (size_t)(row0 + g + 8) * NDIM + col) =
                make_float2(acc[mt][nt][2], acc[mt][nt][3]);
        }
    }
}

// ---------------------------------------------------------------------------
extern "C" void kernel_launch(void* const* d_in, const int* in_sizes, int n_in,
                              void* d_out, int out_size) {
    const float* x     = (const float*)d_in[0];
    const int*   qw    = (const int*)  d_in[1];
    const float* scale = (const float*)d_in[2];
    const float* zero  = (const float*)d_in[3];
    float* out = (float*)d_out;

    xconv_kernel<<<(MDIM * (size_t)KDIM / 4) / 256, 256>>>(x);
    dequant_kernel<<<(NDIM * (size_t)KDIM / 8) / 256, 256>>>(qw, scale, zero);

    cudaFuncSetAttribute(gemm_kernel, cudaFuncAttributeMaxDynamicSharedMemorySize,
                         SMEM_TOTAL);
    dim3 grid(NDIM / BN, MDIM / BM);  // 16 x 64; n-fastest keeps A band + W in L2
    gemm_kernel<<<grid, 256, SMEM_TOTAL>>>(out);
}

// round 8
// speedup vs baseline: 1.0802x; 1.0802x over previous
#include <cuda_runtime.h>
#include <cuda_fp16.h>
#include <cstdint>

// Problem dims: x (4,2048,4096) fp32 -> M=8192, qweight (4096,2048) int32,
// scale/zero (4096,32) fp32, out (8192,4096) fp32.
#define MDIM 8192
#define NDIM 4096
#define KDIM 4096
#define GROUPS 32

// Scratch (allocation-free rule: __device__ globals)
__device__ __align__(256) __half g_xh[(size_t)MDIM * KDIM];  // 64 MB
__device__ __align__(256) __half g_wh[(size_t)NDIM * KDIM];  // 32 MB

// ---------------------------------------------------------------------------
// Prep kernel 1: x fp32 -> fp16
// ---------------------------------------------------------------------------
__global__ void xconv_kernel(const float* __restrict__ x) {
    int i = blockIdx.x * blockDim.x + threadIdx.x;
    float4 v = reinterpret_cast<const float4*>(x)[i];
    union { uint2 u; __half2 h[2]; } pk;
    pk.h[0] = __floats2half2_rn(v.x, v.y);
    pk.h[1] = __floats2half2_rn(v.z, v.w);
    reinterpret_cast<uint2*>(g_xh)[i] = pk.u;
}

// ---------------------------------------------------------------------------
// Prep kernel 2: int4 group-dequant -> fp16 weights
// ---------------------------------------------------------------------------
__global__ void dequant_kernel(const int* __restrict__ qw,
                               const float* __restrict__ scale,
                               const float* __restrict__ zero) {
    int i = blockIdx.x * blockDim.x + threadIdx.x;
    int4 q = reinterpret_cast<const int4*>(qw)[i];
    int o  = i >> 9;
    int j4 = i & 511;
    int g  = (j4 * 8) >> 7;
    float s = scale[o * GROUPS + g];
    float z = zero [o * GROUPS + g];
    int v[4] = {q.x, q.y, q.z, q.w};
    union { uint4 u; __half2 h[4]; } pk;
#pragma unroll
    for (int t = 0; t < 4; ++t) {
        float lo = (float)( v[t]       & 0xF);
        float hi = (float)((v[t] >> 4) & 0xF);
        pk.h[t] = __floats2half2_rn((lo - z) * s, (hi - z) * s);
    }
    reinterpret_cast<uint4*>(g_wh)[i] = pk.u;
}

// ---------------------------------------------------------------------------
// fp16 GEMM (mma.sync HMMA — tcgen05 rejected by compute_103 PTX target)
// CTA tile 128x128, BK=64, 3-stage cp.async pipeline, ONE sync per iter,
// 2 CTAs/SM, 8 warps (4x2), warp tile 32x64. (R1 addressing, proven.)
// ---------------------------------------------------------------------------
#define BM 128
#define BN 128
#define BK 64
#define NK (KDIM / BK)   // 64
#define STAGES 3
#define A_HALF (BM * BK)              // 8192 halves = 16 KB
#define B_HALF (BN * BK)
#define STAGE_HALF (A_HALF + B_HALF)  // 32 KB
#define SMEM_TOTAL (STAGES * STAGE_HALF * 2)  // 98304 B -> 2 CTAs/SM

__device__ __forceinline__ void cp16(uint32_t s, const void* g) {
    asm volatile("cp.async.cg.shared.global [%0], [%1], 16;" :: "r"(s), "l"(g));
}
__device__ __forceinline__ void ldsm4(uint32_t& r0, uint32_t& r1, uint32_t& r2,
                                      uint32_t& r3, const __half* p) {
    uint32_t s = (uint32_t)__cvta_generic_to_shared(p);
    asm volatile("ldmatrix.sync.aligned.m8n8.x4.shared.b16 {%0,%1,%2,%3}, [%4];"
                 : "=r"(r0), "=r"(r1), "=r"(r2), "=r"(r3) : "r"(s));
}
__device__ __forceinline__ void mma16816(float* d, const uint32_t* a, const uint32_t* b) {
    asm volatile(
        "mma.sync.aligned.m16n8k16.row.col.f32.f16.f16.f32 "
        "{%0,%1,%2,%3}, {%4,%5,%6,%7}, {%8,%9}, {%0,%1,%2,%3};"
        : "+f"(d[0]), "+f"(d[1]), "+f"(d[2]), "+f"(d[3])
        : "r"(a[0]), "r"(a[1]), "r"(a[2]), "r"(a[3]), "r"(b[0]), "r"(b[1]));
}

__global__ void __launch_bounds__(256, 2) gemm_kernel(float* __restrict__ out) {
    extern __shared__ __half smem[];

    const int tid  = threadIdx.x;
    const int warp = tid >> 5;
    const int lane = tid & 31;
    const int wm = warp >> 1;   // 0..3 (32-row band)
    const int wn = warp & 1;    // 0..1 (64-col band)
    const int m0 = blockIdx.y * BM;
    const int n0 = blockIdx.x * BN;

    const __half* gA = g_xh + (size_t)m0 * KDIM;
    const __half* gB = g_wh + (size_t)n0 * KDIM;

    const int ldRow = tid >> 3;  // 0..31
    const int ldCh  = tid & 7;   // 16B chunk within 128B row

    float acc[2][8][4];
#pragma unroll
    for (int mt = 0; mt < 2; ++mt)
#pragma unroll
        for (int nt = 0; nt < 8; ++nt)
#pragma unroll
            for (int r = 0; r < 4; ++r) acc[mt][nt][r] = 0.0f;

    // --- stage loader (SW128 swizzle: chunk ^= row&7); 8 cp16/thread ---
    auto stage = [&](int buf, int k0) {
        __half* sA = smem + buf * STAGE_HALF;
        __half* sB = sA + A_HALF;
        uint32_t sAb = (uint32_t)__cvta_generic_to_shared(sA);
        uint32_t sBb = (uint32_t)__cvta_generic_to_shared(sB);
        const int sw = (ldCh ^ (ldRow & 7)) * 8;  // ldRow&7 invariant under +32
#pragma unroll
        for (int p = 0; p < 4; ++p) {
            int r = ldRow + p * 32;
            cp16(sAb + (uint32_t)(r * BK + sw) * 2, gA + (size_t)r * KDIM + k0 + ldCh * 8);
            cp16(sBb + (uint32_t)(r * BK + sw) * 2, gB + (size_t)r * KDIM + k0 + ldCh * 8);
        }
        asm volatile("cp.async.commit_group;");
    };

    // prologue: fill stages 0,1
    stage(0, 0);
    stage(1, BK);

    for (int kt = 0; kt < NK; ++kt) {
        const int buf = kt % STAGES;
        // stage kt must be complete: <=2 groups in flight here; keep <=1.
        if (kt == NK - 1) asm volatile("cp.async.wait_group 0;");
        else              asm volatile("cp.async.wait_group 1;");
        __syncthreads();   // SINGLE barrier per iteration

        const __half* bufA = smem + buf * STAGE_HALF;
        const __half* bufB = bufA + A_HALF;

#pragma unroll
        for (int ks = 0; ks < BK / 16; ++ks) {
            uint32_t aF[2][4];
#pragma unroll
            for (int mt = 0; mt < 2; ++mt) {
                int r  = wm * 32 + mt * 16 + (lane & 15);
                int ch = ks * 2 + (lane >> 4);
                const __half* p = bufA + r * BK + ((ch ^ (lane & 7)) * 8);
                ldsm4(aF[mt][0], aF[mt][1], aF[mt][2], aF[mt][3], p);
            }
            uint32_t bF[8][2];
#pragma unroll
            for (int nt2 = 0; nt2 < 4; ++nt2) {
                int r  = wn * 64 + nt2 * 16 + (lane & 7) + ((lane >> 4) << 3);
                int ch = ks * 2 + ((lane >> 3) & 1);
                const __half* p = bufB + r * BK + ((ch ^ (lane & 7)) * 8);
                uint32_t r0, r1, r2, r3;
                ldsm4(r0, r1, r2, r3, p);
                bF[nt2 * 2 + 0][0] = r0; bF[nt2 * 2 + 0][1] = r1;
                bF[nt2 * 2 + 1][0] = r2; bF[nt2 * 2 + 1][1] = r3;
            }
#pragma unroll
            for (int mt = 0; mt < 2; ++mt)
#pragma unroll
                for (int nt = 0; nt < 8; ++nt)
                    mma16816(acc[mt][nt], aF[mt], bF[nt]);
        }

        // prefetch stage kt+2 into buf (kt+2)%3 == (kt-1)%3 (readers done:
        // guaranteed by this iteration's barrier above)
        if (kt + STAGES - 1 < NK)
            stage((kt + STAGES - 1) % STAGES, (kt + STAGES - 1) * BK);
    }

    // --- epilogue: fp32 direct stores ---
    const int g  = lane >> 2;
    const int tg = lane & 3;
#pragma unroll
    for (int mt = 0; mt < 2; ++mt) {
        int row0 = m0 + wm * 32 + mt * 16;
#pragma unroll
        for (int nt = 0; nt < 8; ++nt) {
            int col = n0 + wn * 64 + nt * 8 + tg * 2;
            *reinterpret_cast<float2*>(out + (size_t)(row0 + g) * NDIM + col) =
                make_float2(acc[mt][nt][0], acc[mt][nt][1]);
            *reinterpret_cast<float2*>(out + (size_t)(row0 + g + 8) * NDIM + col) =
                make_float2(acc[mt][nt][2], acc[mt][nt][3]);
        }
    }
}

// ---------------------------------------------------------------------------
extern "C" void kernel_launch(void* const* d_in, const int* in_sizes, int n_in,
                              void* d_out, int out_size) {
    const float* x     = (const float*)d_in[0];
    const int*   qw    = (const int*)  d_in[1];
    const float* scale = (const float*)d_in[2];
    const float* zero  = (const float*)d_in[3];
    float* out = (float*)d_out;

    xconv_kernel<<<(MDIM * (size_t)KDIM / 4) / 256, 256>>>(x);
    dequant_kernel<<<(NDIM * (size_t)KDIM / 8) / 256, 256>>>(qw, scale, zero);

    cudaFuncSetAttribute(gemm_kernel, cudaFuncAttributeMaxDynamicSharedMemorySize,
                         SMEM_TOTAL);
    dim3 grid(NDIM / BN, MDIM / BM);  // 32 x 64; n-fastest keeps A band + W in L2
    gemm_kernel<<<grid, 256, SMEM_TOTAL>>>(out);
}

// round 9
// speedup vs baseline: 1.1561x; 1.0703x over previous
#include <cuda_runtime.h>
#include <cuda_fp16.h>
#include <cstdint>

// Problem dims: x (4,2048,4096) fp32 -> M=8192, qweight (4096,2048) int32,
// scale/zero (4096,32) fp32, out (8192,4096) fp32.
#define MDIM 8192
#define NDIM 4096
#define KDIM 4096
#define GROUPS 32

// Scratch (allocation-free rule: __device__ globals)
__device__ __align__(256) __half g_xh[(size_t)MDIM * KDIM];  // 64 MB
__device__ __align__(256) __half g_wh[(size_t)NDIM * KDIM];  // 32 MB

// ---------------------------------------------------------------------------
// Prep kernel 1: x fp32 -> fp16
// ---------------------------------------------------------------------------
__global__ void xconv_kernel(const float* __restrict__ x) {
    int i = blockIdx.x * blockDim.x + threadIdx.x;
    float4 v = reinterpret_cast<const float4*>(x)[i];
    union { uint2 u; __half2 h[2]; } pk;
    pk.h[0] = __floats2half2_rn(v.x, v.y);
    pk.h[1] = __floats2half2_rn(v.z, v.w);
    reinterpret_cast<uint2*>(g_xh)[i] = pk.u;
}

// ---------------------------------------------------------------------------
// Prep kernel 2: int4 group-dequant -> fp16 weights
// ---------------------------------------------------------------------------
__global__ void dequant_kernel(const int* __restrict__ qw,
                               const float* __restrict__ scale,
                               const float* __restrict__ zero) {
    int i = blockIdx.x * blockDim.x + threadIdx.x;
    int4 q = reinterpret_cast<const int4*>(qw)[i];
    int o  = i >> 9;
    int j4 = i & 511;
    int g  = (j4 * 8) >> 7;
    float s = scale[o * GROUPS + g];
    float z = zero [o * GROUPS + g];
    int v[4] = {q.x, q.y, q.z, q.w};
    union { uint4 u; __half2 h[4]; } pk;
#pragma unroll
    for (int t = 0; t < 4; ++t) {
        float lo = (float)( v[t]       & 0xF);
        float hi = (float)((v[t] >> 4) & 0xF);
        pk.h[t] = __floats2half2_rn((lo - z) * s, (hi - z) * s);
    }
    reinterpret_cast<uint4*>(g_wh)[i] = pk.u;
}

// ---------------------------------------------------------------------------
// fp16 GEMM (mma.sync HMMA — tcgen05 rejected by compute_103 PTX target)
// CTA tile 128x128, BK=64, 3-stage cp.async pipeline, single sync per iter,
// 4 warps (2x2), warp tile 64x64 -> smem reads 64KB/iter (was 96KB),
// 2 CTAs/SM (96 KB smem each).
// ---------------------------------------------------------------------------
#define BM 128
#define BN 128
#define BK 64
#define NK (KDIM / BK)   // 64
#define STAGES 3
#define NTHREADS 128
#define A_HALF (BM * BK)              // 8192 halves = 16 KB
#define B_HALF (BN * BK)
#define STAGE_HALF (A_HALF + B_HALF)  // 32 KB
#define SMEM_TOTAL (STAGES * STAGE_HALF * 2)  // 98304 B -> 2 CTAs/SM

__device__ __forceinline__ void cp16(uint32_t s, const void* g) {
    asm volatile("cp.async.cg.shared.global [%0], [%1], 16;" :: "r"(s), "l"(g));
}
__device__ __forceinline__ void ldsm4(uint32_t& r0, uint32_t& r1, uint32_t& r2,
                                      uint32_t& r3, const __half* p) {
    uint32_t s = (uint32_t)__cvta_generic_to_shared(p);
    asm volatile("ldmatrix.sync.aligned.m8n8.x4.shared.b16 {%0,%1,%2,%3}, [%4];"
                 : "=r"(r0), "=r"(r1), "=r"(r2), "=r"(r3) : "r"(s));
}
__device__ __forceinline__ void mma16816(float* d, const uint32_t* a, const uint32_t* b) {
    asm volatile(
        "mma.sync.aligned.m16n8k16.row.col.f32.f16.f16.f32 "
        "{%0,%1,%2,%3}, {%4,%5,%6,%7}, {%8,%9}, {%0,%1,%2,%3};"
        : "+f"(d[0]), "+f"(d[1]), "+f"(d[2]), "+f"(d[3])
        : "r"(a[0]), "r"(a[1]), "r"(a[2]), "r"(a[3]), "r"(b[0]), "r"(b[1]));
}

__global__ void __launch_bounds__(NTHREADS, 2) gemm_kernel(float* __restrict__ out) {
    extern __shared__ __half smem[];

    const int tid  = threadIdx.x;
    const int warp = tid >> 5;
    const int lane = tid & 31;
    const int wm = warp >> 1;   // 0..1 (64-row band)
    const int wn = warp & 1;    // 0..1 (64-col band)
    const int m0 = blockIdx.y * BM;
    const int n0 = blockIdx.x * BN;

    const __half* gA = g_xh + (size_t)m0 * KDIM;
    const __half* gB = g_wh + (size_t)n0 * KDIM;

    const int ldRow = tid >> 3;  // 0..15
    const int ldCh  = tid & 7;   // 16B chunk within 128B row

    float acc[4][8][4];
#pragma unroll
    for (int mt = 0; mt < 4; ++mt)
#pragma unroll
        for (int nt = 0; nt < 8; ++nt)
#pragma unroll
            for (int r = 0; r < 4; ++r) acc[mt][nt][r] = 0.0f;

    // --- stage loader (SW128 swizzle: chunk ^= row&7); 16 cp16/thread ---
    auto stage = [&](int buf, int k0) {
        __half* sA = smem + buf * STAGE_HALF;
        __half* sB = sA + A_HALF;
        uint32_t sAb = (uint32_t)__cvta_generic_to_shared(sA);
        uint32_t sBb = (uint32_t)__cvta_generic_to_shared(sB);
        const int sw = (ldCh ^ (ldRow & 7)) * 8;  // ldRow&7 invariant under +16
#pragma unroll
        for (int p = 0; p < 8; ++p) {
            int r = ldRow + p * 16;
            cp16(sAb + (uint32_t)(r * BK + sw) * 2, gA + (size_t)r * KDIM + k0 + ldCh * 8);
            cp16(sBb + (uint32_t)(r * BK + sw) * 2, gB + (size_t)r * KDIM + k0 + ldCh * 8);
        }
        asm volatile("cp.async.commit_group;");
    };

    // prologue: fill stages 0,1
    stage(0, 0);
    stage(1, BK);

    for (int kt = 0; kt < NK; ++kt) {
        const int buf = kt % STAGES;
        if (kt == NK - 1) asm volatile("cp.async.wait_group 0;");
        else              asm volatile("cp.async.wait_group 1;");
        __syncthreads();   // single barrier per iteration

        const __half* bufA = smem + buf * STAGE_HALF;
        const __half* bufB = bufA + A_HALF;

#pragma unroll
        for (int ks = 0; ks < BK / 16; ++ks) {
            uint32_t aF[4][4];
#pragma unroll
            for (int mt = 0; mt < 4; ++mt) {
                int r  = wm * 64 + mt * 16 + (lane & 15);
                int ch = ks * 2 + (lane >> 4);
                const __half* p = bufA + r * BK + ((ch ^ (lane & 7)) * 8);
                ldsm4(aF[mt][0], aF[mt][1], aF[mt][2], aF[mt][3], p);
            }
            uint32_t bF[8][2];
#pragma unroll
            for (int nt2 = 0; nt2 < 4; ++nt2) {
                int r  = wn * 64 + nt2 * 16 + (lane & 7) + ((lane >> 4) << 3);
                int ch = ks * 2 + ((lane >> 3) & 1);
                const __half* p = bufB + r * BK + ((ch ^ (lane & 7)) * 8);
                uint32_t r0, r1, r2, r3;
                ldsm4(r0, r1, r2, r3, p);
                bF[nt2 * 2 + 0][0] = r0; bF[nt2 * 2 + 0][1] = r1;
                bF[nt2 * 2 + 1][0] = r2; bF[nt2 * 2 + 1][1] = r3;
            }
#pragma unroll
            for (int mt = 0; mt < 4; ++mt)
#pragma unroll
                for (int nt = 0; nt < 8; ++nt)
                    mma16816(acc[mt][nt], aF[mt], bF[nt]);
        }

        // prefetch stage kt+2 (overwrite legal: all readers passed this
        // iteration's barrier after finishing iter kt-1)
        if (kt + STAGES - 1 < NK)
            stage((kt + STAGES - 1) % STAGES, (kt + STAGES - 1) * BK);
    }

    // --- epilogue: fp32 direct stores ---
    const int g  = lane >> 2;
    const int tg = lane & 3;
#pragma unroll
    for (int mt = 0; mt < 4; ++mt) {
        int row0 = m0 + wm * 64 + mt * 16;
#pragma unroll
        for (int nt = 0; nt < 8; ++nt) {
            int col = n0 + wn * 64 + nt * 8 + tg * 2;
            *reinterpret_cast<float2*>(out + (size_t)(row0 + g) * NDIM + col) =
                make_float2(acc[mt][nt][0], acc[mt][nt][1]);
            *reinterpret_cast<float2*>(out + (size_t)(row0 + g + 8) * NDIM + col) =
                make_float2(acc[mt][nt][2], acc[mt][nt][3]);
        }
    }
}

// ---------------------------------------------------------------------------
extern "C" void kernel_launch(void* const* d_in, const int* in_sizes, int n_in,
                              void* d_out, int out_size) {
    const float* x     = (const float*)d_in[0];
    const int*   qw    = (const int*)  d_in[1];
    const float* scale = (const float*)d_in[2];
    const float* zero  = (const float*)d_in[3];
    float* out = (float*)d_out;

    xconv_kernel<<<(MDIM * (size_t)KDIM / 4) / 256, 256>>>(x);
    dequant_kernel<<<(NDIM * (size_t)KDIM / 8) / 256, 256>>>(qw, scale, zero);

    cudaFuncSetAttribute(gemm_kernel, cudaFuncAttributeMaxDynamicSharedMemorySize,
                         SMEM_TOTAL);
    dim3 grid(NDIM / BN, MDIM / BM);  // 32 x 64; n-fastest keeps A band + W in L2
    gemm_kernel<<<grid, NTHREADS, SMEM_TOTAL>>>(out);
}